// round 3
// baseline (speedup 1.0000x reference)
#include <cuda_runtime.h>
#include <math.h>

#define BB 256
#define SS 512
#define VV 768
#define TT 513   // S + mean row
#define HH 50
#define NSPLIT 4
#define SCHUNK 128  // SS / NSPLIT

// ---------------- scratch (device globals; no allocation allowed) ----------------
__device__ __align__(16) float g_mean1[BB * VV];
__device__ __align__(16) float g_mean2[BB * VV];
__device__ __align__(16) float g_part1[NSPLIT * BB * VV];   // mean1 partials
__device__ __align__(16) float g_part2[NSPLIT * BB * VV];   // mean2 partials
__device__ __align__(16) float g_row[BB * TT];              // row[b,t] = mean1[b] . x2[b,t]
__device__ __align__(16) float g_wy[BB * TT];               // batch-softmax weights
__device__ __align__(16) float g_axpart[NSPLIT * BB * VV];  // online-softmax partial accumulators
__device__ float g_axm[NSPLIT * BB];                        // running max per partial
__device__ float g_axz[NSPLIT * BB];                        // running Z per partial
__device__ __align__(16) float g_aypart[NSPLIT * BB * VV];  // atty partial sums

// ---------------- K1: partial mean of output_1 over s ----------------
__global__ __launch_bounds__(192) void meanPartK(const float* __restrict__ src) {
    int split = blockIdx.x, b = blockIdx.y, tid = threadIdx.x;  // block = 192 = VV/4
    const float4* s4 = (const float4*)src;
    float4 acc = make_float4(0.f, 0.f, 0.f, 0.f);
    size_t base = ((size_t)b * SS + (size_t)split * SCHUNK) * (VV / 4) + tid;
#pragma unroll 4
    for (int t = 0; t < SCHUNK; t++) {
        float4 x = s4[base + (size_t)t * (VV / 4)];
        acc.x += x.x; acc.y += x.y; acc.z += x.z; acc.w += x.w;
    }
    ((float4*)g_part1)[((size_t)split * BB + b) * (VV / 4) + tid] = acc;
}

// ---------------- combine partial sums -> mean ----------------
__global__ __launch_bounds__(256) void combine1K() {
    int i = blockIdx.x * 256 + threadIdx.x;  // N = BB*VV
    float s = g_part1[i] + g_part1[i + BB * VV] + g_part1[i + 2 * BB * VV] + g_part1[i + 3 * BB * VV];
    g_mean1[i] = s * (1.0f / SS);
}
__global__ __launch_bounds__(256) void combine2K() {
    int i = blockIdx.x * 256 + threadIdx.x;
    float s = g_part2[i] + g_part2[i + BB * VV] + g_part2[i + 2 * BB * VV] + g_part2[i + 3 * BB * VV];
    g_mean2[i] = s * (1.0f / SS);
}

// ---------------- K2: fused pass over output_2: mean2 partials + row[b,t] ----------------
__global__ __launch_bounds__(256) void meanRowPartK(const float* __restrict__ src) {
    __shared__ __align__(16) float m_s[VV];
    __shared__ __align__(16) float buf[VV];
    int split = blockIdx.x, b = blockIdx.y, tid = threadIdx.x;
    int wid = tid >> 5, lane = tid & 31;
    for (int i = tid; i < VV; i += 256) m_s[i] = g_mean1[b * VV + i];
    __syncthreads();
    const float4* s4 = (const float4*)src;
    const float4* m4 = (const float4*)m_s;
    float4 macc[6];
#pragma unroll
    for (int j = 0; j < 6; j++) macc[j] = make_float4(0.f, 0.f, 0.f, 0.f);
    int t0 = split * SCHUNK;
    for (int i = 0; i < 16; i++) {
        int t = t0 + wid + 8 * i;
        size_t base = ((size_t)b * SS + t) * (VV / 4);
        float dot = 0.f;
#pragma unroll
        for (int j = 0; j < 6; j++) {
            float4 x = s4[base + lane + 32 * j];
            float4 m = m4[lane + 32 * j];
            dot += x.x * m.x + x.y * m.y + x.z * m.z + x.w * m.w;
            macc[j].x += x.x; macc[j].y += x.y; macc[j].z += x.z; macc[j].w += x.w;
        }
#pragma unroll
        for (int o = 16; o; o >>= 1) dot += __shfl_xor_sync(0xffffffffu, dot, o);
        if (lane == 0) g_row[b * TT + t] = dot;
    }
    // cross-warp reduce of per-lane column partial sums
    float4* b4 = (float4*)buf;
    for (int w = 0; w < 8; w++) {
        if (wid == w) {
#pragma unroll
            for (int j = 0; j < 6; j++) {
                if (w == 0) b4[lane + 32 * j] = macc[j];
                else {
                    float4 t2 = b4[lane + 32 * j];
                    t2.x += macc[j].x; t2.y += macc[j].y; t2.z += macc[j].z; t2.w += macc[j].w;
                    b4[lane + 32 * j] = t2;
                }
            }
        }
        __syncthreads();
    }
    for (int i = tid; i < VV; i += 256) g_part2[((size_t)split * BB + b) * VV + i] = buf[i];
}

// ---------------- K3a: row[b,512] = mean1[b] . mean2[b] ----------------
__global__ __launch_bounds__(256) void row512K() {
    int wid = threadIdx.x >> 5, lane = threadIdx.x & 31;
    int b = blockIdx.x * 8 + wid;  // grid = BB/8
    float dot = 0.f;
    for (int j = lane; j < VV; j += 32) dot += g_mean1[b * VV + j] * g_mean2[b * VV + j];
#pragma unroll
    for (int o = 16; o; o >>= 1) dot += __shfl_xor_sync(0xffffffffu, dot, o);
    if (lane == 0) g_row[b * TT + 512] = dot;
}

// ---------------- K3b: softmax over batch axis for each t ----------------
__global__ __launch_bounds__(256) void softmaxBK() {
    int t = blockIdx.x;          // grid = TT
    int b = threadIdx.x;         // block = BB
    __shared__ float red[BB];
    float v = g_row[b * TT + t];
    red[b] = v; __syncthreads();
    for (int o = 128; o; o >>= 1) { if (b < o) red[b] = fmaxf(red[b], red[b + o]); __syncthreads(); }
    float m = red[0]; __syncthreads();
    float e = __expf(v - m);
    red[b] = e; __syncthreads();
    for (int o = 128; o; o >>= 1) { if (b < o) red[b] += red[b + o]; __syncthreads(); }
    float Z = red[0];
    g_wy[b * TT + t] = e / Z;
}

// ---------------- K4: online-softmax weighted sum over output_1 (attention_x last row) ----------------
__global__ __launch_bounds__(256) void attxPartK(const float* __restrict__ src) {
    __shared__ __align__(16) float m_s[VV];
    __shared__ __align__(16) float chunk[8 * VV];
    __shared__ float sdots[8];
    int split = blockIdx.x, b = blockIdx.y, tid = threadIdx.x;
    int wid = tid >> 5, lane = tid & 31;
    for (int i = tid; i < VV; i += 256) m_s[i] = g_mean2[b * VV + i];
    __syncthreads();
    const float4* s4 = (const float4*)src;
    const float4* m4 = (const float4*)m_s;
    float acc0 = 0.f, acc1 = 0.f, acc2 = 0.f;
    float runmax = -1e30f, Z = 0.f;
    int s0 = split * SCHUNK;
    for (int c = 0; c < 16; c++) {
        size_t base = ((size_t)b * SS + s0 + c * 8) * (VV / 4);
        float4* ch4 = (float4*)chunk;
#pragma unroll
        for (int k = 0; k < 6; k++) ch4[tid + 256 * k] = s4[base + tid + 256 * k];
        __syncthreads();
        float dot = 0.f;
#pragma unroll
        for (int j = 0; j < 6; j++) {
            float4 x = ((const float4*)chunk)[wid * (VV / 4) + lane + 32 * j];
            float4 m = m4[lane + 32 * j];
            dot += x.x * m.x + x.y * m.y + x.z * m.z + x.w * m.w;
        }
#pragma unroll
        for (int o = 16; o; o >>= 1) dot += __shfl_xor_sync(0xffffffffu, dot, o);
        if (lane == 0) sdots[wid] = dot;
        __syncthreads();
        float cm = sdots[0];
#pragma unroll
        for (int r = 1; r < 8; r++) cm = fmaxf(cm, sdots[r]);
        float nm = fmaxf(runmax, cm);
        float scale = __expf(runmax - nm);
        float w[8]; float wsum = 0.f;
#pragma unroll
        for (int r = 0; r < 8; r++) { w[r] = __expf(sdots[r] - nm); wsum += w[r]; }
        Z = Z * scale + wsum;
        acc0 *= scale; acc1 *= scale; acc2 *= scale;
#pragma unroll
        for (int r = 0; r < 8; r++) {
            acc0 += w[r] * chunk[r * VV + tid];
            acc1 += w[r] * chunk[r * VV + tid + 256];
            acc2 += w[r] * chunk[r * VV + tid + 512];
        }
        runmax = nm;
        __syncthreads();
    }
    size_t ob = (size_t)split * BB + b;
    g_axpart[ob * VV + tid] = acc0;
    g_axpart[ob * VV + tid + 256] = acc1;
    g_axpart[ob * VV + tid + 512] = acc2;
    if (tid == 0) { g_axm[ob] = runmax; g_axz[ob] = Z; }
}

// ---------------- K5: weighted sum over output_2 (attention_y last row) ----------------
__global__ __launch_bounds__(192) void attyPartK(const float* __restrict__ src) {
    __shared__ float wy_s[SCHUNK];
    int split = blockIdx.x, b = blockIdx.y, tid = threadIdx.x;  // block = 192
    int t0 = split * SCHUNK;
    for (int i = tid; i < SCHUNK; i += 192) wy_s[i] = g_wy[b * TT + t0 + i];
    __syncthreads();
    const float4* s4 = (const float4*)src;
    float4 acc = make_float4(0.f, 0.f, 0.f, 0.f);
    size_t base = ((size_t)b * SS + t0) * (VV / 4) + tid;
#pragma unroll 4
    for (int t = 0; t < SCHUNK; t++) {
        float w = wy_s[t];
        float4 x = s4[base + (size_t)t * (VV / 4)];
        acc.x += w * x.x; acc.y += w * x.y; acc.z += w * x.z; acc.w += w * x.w;
    }
    ((float4*)g_aypart)[((size_t)split * BB + b) * (VV / 4) + tid] = acc;
}

// ---------------- K6: combine partials + full MLP head ----------------
__global__ __launch_bounds__(256) void finalK(const float* __restrict__ Wg, const float* __restrict__ bg,
                                              const float* __restrict__ Wfd, const float* __restrict__ bfd,
                                              const float* __restrict__ Wff, const float* __restrict__ bff,
                                              float* __restrict__ out) {
    int b = blockIdx.x, tid = threadIdx.x, wid = tid >> 5, lane = tid & 31;
    __shared__ float c1[2 * VV];   // [mean1 , atty]
    __shared__ float c2[2 * VV];   // [mean2 , attx]
    __shared__ float o_s[2 * HH];
    __shared__ float h_s[HH];
    float col512 = g_row[b * TT + 512];
    float wy512 = g_wy[b * TT + 512];
    float m[NSPLIT], z[NSPLIT];
#pragma unroll
    for (int i = 0; i < NSPLIT; i++) { m[i] = g_axm[i * BB + b]; z[i] = g_axz[i * BB + b]; }
    float M = col512;
#pragma unroll
    for (int i = 0; i < NSPLIT; i++) M = fmaxf(M, m[i]);
    float e5 = __expf(col512 - M);
    float Ztot = e5;
    float e[NSPLIT];
#pragma unroll
    for (int i = 0; i < NSPLIT; i++) { e[i] = __expf(m[i] - M); Ztot += e[i] * z[i]; }
    float inv = 1.f / Ztot;
    for (int v = tid; v < VV; v += 256) {
        float m1v = g_mean1[b * VV + v];
        float m2v = g_mean2[b * VV + v];
        float ax = e5 * m1v;
        float ay = wy512 * m2v;
#pragma unroll
        for (int i = 0; i < NSPLIT; i++) {
            ax += e[i] * g_axpart[((size_t)i * BB + b) * VV + v];
            ay += g_aypart[((size_t)i * BB + b) * VV + v];
        }
        c1[v] = m1v; c1[VV + v] = ay;
        c2[v] = m2v; c2[VV + v] = ax * inv;
    }
    __syncthreads();
    // o1/o2: 100 dot products of length 1536 against Wg rows
    for (int task = wid; task < 2 * HH; task += 8) {
        int which = task >= HH;
        int h = which ? task - HH : task;
        const float* c = which ? c2 : c1;
        float dot = 0.f;
        for (int j = lane; j < 2 * VV; j += 32) dot += Wg[h * 2 * VV + j] * c[j];
#pragma unroll
        for (int o = 16; o; o >>= 1) dot += __shfl_xor_sync(0xffffffffu, dot, o);
        if (lane == 0) o_s[which * HH + h] = bg[h] + dot;
    }
    __syncthreads();
    if (tid < HH) {
        float hv = bfd[tid];
#pragma unroll 4
        for (int k = 0; k < 2 * HH; k++) hv += Wfd[tid * 2 * HH + k] * o_s[k];
        h_s[tid] = fmaxf(hv, 0.f);
    }
    __syncthreads();
    if (tid == 0) {
        float l = bff[0];
#pragma unroll 5
        for (int j = 0; j < HH; j++) l += Wff[j] * h_s[j];
        out[b] = 1.f / (1.f + expf(-l));
    }
}

// ---------------- launch ----------------
extern "C" void kernel_launch(void* const* d_in, const int* in_sizes, int n_in,
                              void* d_out, int out_size) {
    const float* out1 = (const float*)d_in[0];
    const float* out2 = (const float*)d_in[1];
    const float* Wg  = (const float*)d_in[2];
    const float* bg  = (const float*)d_in[3];
    const float* Wfd = (const float*)d_in[4];
    const float* bfd = (const float*)d_in[5];
    const float* Wff = (const float*)d_in[6];
    const float* bff = (const float*)d_in[7];
    float* out = (float*)d_out;

    dim3 gp(NSPLIT, BB);
    meanPartK<<<gp, 192>>>(out1);
    combine1K<<<(BB * VV) / 256, 256>>>();
    meanRowPartK<<<gp, 256>>>(out2);
    combine2K<<<(BB * VV) / 256, 256>>>();
    row512K<<<BB / 8, 256>>>();
    softmaxBK<<<TT, 256>>>();
    attxPartK<<<gp, 256>>>(out1);
    attyPartK<<<gp, 192>>>(out2);
    finalK<<<BB, 256>>>(Wg, bg, Wfd, bfd, Wff, bff, out);
}

// round 5
// speedup vs baseline: 1.1241x; 1.1241x over previous
#include <cuda_runtime.h>
#include <math.h>

#define BB 256
#define SS 512
#define VV 768
#define TT 513   // S + mean row
#define HH 50
#define NSPLIT 4
#define SCHUNK 128  // SS / NSPLIT

// ---------------- scratch (device globals; no allocation allowed) ----------------
__device__ __align__(16) float g_mean1[BB * VV];
__device__ __align__(16) float g_mean2[BB * VV];
__device__ __align__(16) float g_part1[NSPLIT * BB * VV];   // mean1 partials
__device__ __align__(16) float g_part2[NSPLIT * BB * VV];   // mean2 partials
__device__ __align__(16) float g_row[BB * TT];              // row[b,t] = mean1[b] . x2[b,t]
__device__ __align__(16) float g_wy[BB * TT];               // batch-softmax weights
__device__ __align__(16) float g_axpart[NSPLIT * BB * VV];  // online-softmax partial accumulators
__device__ float g_axm[NSPLIT * BB];                        // running max per partial
__device__ float g_axz[NSPLIT * BB];                        // running Z per partial
__device__ __align__(16) float g_aypart[NSPLIT * BB * VV];  // atty partial sums

// ---------------- K1: partial mean of output_1 over s (unroll-8, split accumulators) ----------------
__global__ __launch_bounds__(192) void meanPartK(const float* __restrict__ src) {
    int split = blockIdx.x, b = blockIdx.y, tid = threadIdx.x;  // block = 192 = VV/4
    const float4* s4 = (const float4*)src;
    float4 a0 = make_float4(0.f, 0.f, 0.f, 0.f);
    float4 a1 = make_float4(0.f, 0.f, 0.f, 0.f);
    size_t base = ((size_t)b * SS + (size_t)split * SCHUNK) * (VV / 4) + tid;
    for (int t = 0; t < SCHUNK; t += 8) {
        float4 x[8];
#pragma unroll
        for (int k = 0; k < 8; k++) x[k] = s4[base + (size_t)(t + k) * (VV / 4)];
#pragma unroll
        for (int k = 0; k < 8; k += 2) {
            a0.x += x[k].x;   a0.y += x[k].y;   a0.z += x[k].z;   a0.w += x[k].w;
            a1.x += x[k+1].x; a1.y += x[k+1].y; a1.z += x[k+1].z; a1.w += x[k+1].w;
        }
    }
    a0.x += a1.x; a0.y += a1.y; a0.z += a1.z; a0.w += a1.w;
    ((float4*)g_part1)[((size_t)split * BB + b) * (VV / 4) + tid] = a0;
}

// ---------------- K2: fused pass over output_2: mean2 partials + row[b,t] ----------------
// Prologue reduces mean1 locally from g_part1 (L2-hot; replaces combine1K launch).
__global__ __launch_bounds__(256) void meanRowPartK(const float* __restrict__ src) {
    __shared__ __align__(16) float m_s[VV];
    __shared__ __align__(16) float buf[VV];
    int split = blockIdx.x, b = blockIdx.y, tid = threadIdx.x;
    int wid = tid >> 5, lane = tid & 31;
    for (int i = tid; i < VV; i += 256) {
        float s = g_part1[(size_t)b * VV + i]
                + g_part1[((size_t)BB + b) * VV + i]
                + g_part1[((size_t)2 * BB + b) * VV + i]
                + g_part1[((size_t)3 * BB + b) * VV + i];
        m_s[i] = s * (1.0f / SS);
    }
    __syncthreads();
    const float4* s4 = (const float4*)src;
    const float4* m4 = (const float4*)m_s;
    float4 macc[6];
#pragma unroll
    for (int j = 0; j < 6; j++) macc[j] = make_float4(0.f, 0.f, 0.f, 0.f);
    int t0 = split * SCHUNK;
    for (int i = 0; i < 16; i++) {
        int t = t0 + wid + 8 * i;
        size_t base = ((size_t)b * SS + t) * (VV / 4);
        float dot = 0.f;
#pragma unroll
        for (int j = 0; j < 6; j++) {
            float4 x = s4[base + lane + 32 * j];
            float4 m = m4[lane + 32 * j];
            dot += x.x * m.x + x.y * m.y + x.z * m.z + x.w * m.w;
            macc[j].x += x.x; macc[j].y += x.y; macc[j].z += x.z; macc[j].w += x.w;
        }
#pragma unroll
        for (int o = 16; o; o >>= 1) dot += __shfl_xor_sync(0xffffffffu, dot, o);
        if (lane == 0) g_row[b * TT + t] = dot;
    }
    // cross-warp reduce of per-lane column partial sums
    float4* b4 = (float4*)buf;
    for (int w = 0; w < 8; w++) {
        if (wid == w) {
#pragma unroll
            for (int j = 0; j < 6; j++) {
                if (w == 0) b4[lane + 32 * j] = macc[j];
                else {
                    float4 t2 = b4[lane + 32 * j];
                    t2.x += macc[j].x; t2.y += macc[j].y; t2.z += macc[j].z; t2.w += macc[j].w;
                    b4[lane + 32 * j] = t2;
                }
            }
        }
        __syncthreads();
    }
    for (int i = tid; i < VV; i += 256) g_part2[((size_t)split * BB + b) * VV + i] = buf[i];
}

// ---------------- K3: prep — materialize mean1/mean2 and row[b,512] (replaces combine1K+combine2K+row512K) ----------------
__global__ __launch_bounds__(256) void prepK() {
    __shared__ __align__(16) float m1s[VV];
    __shared__ __align__(16) float m2s[VV];
    __shared__ float red[8];
    int b = blockIdx.x, tid = threadIdx.x, wid = tid >> 5, lane = tid & 31;
    for (int i = tid; i < VV; i += 256) {
        float s1 = g_part1[(size_t)b * VV + i]
                 + g_part1[((size_t)BB + b) * VV + i]
                 + g_part1[((size_t)2 * BB + b) * VV + i]
                 + g_part1[((size_t)3 * BB + b) * VV + i];
        float s2 = g_part2[(size_t)b * VV + i]
                 + g_part2[((size_t)BB + b) * VV + i]
                 + g_part2[((size_t)2 * BB + b) * VV + i]
                 + g_part2[((size_t)3 * BB + b) * VV + i];
        float m1 = s1 * (1.0f / SS), m2 = s2 * (1.0f / SS);
        g_mean1[(size_t)b * VV + i] = m1;
        g_mean2[(size_t)b * VV + i] = m2;
        m1s[i] = m1; m2s[i] = m2;
    }
    __syncthreads();
    float dot = 0.f;
    for (int i = tid; i < VV; i += 256) dot += m1s[i] * m2s[i];
#pragma unroll
    for (int o = 16; o; o >>= 1) dot += __shfl_xor_sync(0xffffffffu, dot, o);
    if (lane == 0) red[wid] = dot;
    __syncthreads();
    if (tid == 0) {
        float s = red[0];
#pragma unroll
        for (int w = 1; w < 8; w++) s += red[w];
        g_row[b * TT + 512] = s;
    }
}

// ---------------- K4: softmax over batch axis for each t ----------------
__global__ __launch_bounds__(256) void softmaxBK() {
    int t = blockIdx.x;          // grid = TT
    int b = threadIdx.x;         // block = BB
    __shared__ float red[BB];
    float v = g_row[b * TT + t];
    red[b] = v; __syncthreads();
    for (int o = 128; o; o >>= 1) { if (b < o) red[b] = fmaxf(red[b], red[b + o]); __syncthreads(); }
    float m = red[0]; __syncthreads();
    float e = __expf(v - m);
    red[b] = e; __syncthreads();
    for (int o = 128; o; o >>= 1) { if (b < o) red[b] += red[b + o]; __syncthreads(); }
    float Z = red[0];
    g_wy[b * TT + t] = e / Z;
}

// ---------------- K5 (fused): z=0 attx over output_1 (online softmax, reg double-buffer)
//                             z=1 atty over output_2 (weighted sum, unroll 8) ----------------
__global__ __launch_bounds__(256) void attK(const float* __restrict__ out1, const float* __restrict__ out2) {
    __shared__ __align__(16) float m_s[VV];
    __shared__ __align__(16) float chunk[8 * VV];
    __shared__ float sdots[8];
    int split = blockIdx.x, b = blockIdx.y, tid = threadIdx.x;
    int wid = tid >> 5, lane = tid & 31;

    if (blockIdx.z == 1) {
        // ---- atty: acc[v] += wy[t] * out2[b,t,v] ----
        __shared__ float wy_s[SCHUNK];
        int t0 = split * SCHUNK;
        if (tid < SCHUNK) wy_s[tid] = g_wy[b * TT + t0 + tid];
        __syncthreads();
        if (tid < VV / 4) {
            const float4* s4 = (const float4*)out2;
            float4 a0 = make_float4(0.f, 0.f, 0.f, 0.f);
            float4 a1 = make_float4(0.f, 0.f, 0.f, 0.f);
            size_t base = ((size_t)b * SS + t0) * (VV / 4) + tid;
            for (int t = 0; t < SCHUNK; t += 8) {
                float4 x[8]; float w[8];
#pragma unroll
                for (int k = 0; k < 8; k++) { x[k] = s4[base + (size_t)(t + k) * (VV / 4)]; w[k] = wy_s[t + k]; }
#pragma unroll
                for (int k = 0; k < 8; k += 2) {
                    a0.x += w[k] * x[k].x;     a0.y += w[k] * x[k].y;     a0.z += w[k] * x[k].z;     a0.w += w[k] * x[k].w;
                    a1.x += w[k+1] * x[k+1].x; a1.y += w[k+1] * x[k+1].y; a1.z += w[k+1] * x[k+1].z; a1.w += w[k+1] * x[k+1].w;
                }
            }
            a0.x += a1.x; a0.y += a1.y; a0.z += a1.z; a0.w += a1.w;
            ((float4*)g_aypart)[((size_t)split * BB + b) * (VV / 4) + tid] = a0;
        }
        return;
    }

    // ---- attx: online softmax over s of (out1[b,s,:] . mean2[b]) with weighted accumulation ----
    for (int i = tid; i < VV; i += 256) m_s[i] = g_mean2[(size_t)b * VV + i];
    __syncthreads();
    const float4* s4 = (const float4*)out1;
    const float4* m4 = (const float4*)m_s;
    float4* ch4 = (float4*)chunk;
    float acc0 = 0.f, acc1 = 0.f, acc2 = 0.f;
    float runmax = -1e30f, Z = 0.f;
    int s0 = split * SCHUNK;

    float4 r[6];
    {   // prefetch chunk 0
        size_t base = ((size_t)b * SS + s0) * (VV / 4);
#pragma unroll
        for (int k = 0; k < 6; k++) r[k] = s4[base + tid + 256 * k];
    }
    for (int c = 0; c < 16; c++) {
#pragma unroll
        for (int k = 0; k < 6; k++) ch4[tid + 256 * k] = r[k];
        __syncthreads();
        if (c < 15) {   // prefetch next chunk while computing this one
            size_t base = ((size_t)b * SS + s0 + (c + 1) * 8) * (VV / 4);
#pragma unroll
            for (int k = 0; k < 6; k++) r[k] = s4[base + tid + 256 * k];
        }
        float dot = 0.f;
#pragma unroll
        for (int j = 0; j < 6; j++) {
            float4 x = ((const float4*)chunk)[wid * (VV / 4) + lane + 32 * j];
            float4 m = m4[lane + 32 * j];
            dot += x.x * m.x + x.y * m.y + x.z * m.z + x.w * m.w;
        }
#pragma unroll
        for (int o = 16; o; o >>= 1) dot += __shfl_xor_sync(0xffffffffu, dot, o);
        if (lane == 0) sdots[wid] = dot;
        __syncthreads();
        float cm = sdots[0];
#pragma unroll
        for (int rr = 1; rr < 8; rr++) cm = fmaxf(cm, sdots[rr]);
        float nm = fmaxf(runmax, cm);
        float scale = __expf(runmax - nm);
        float w[8]; float wsum = 0.f;
#pragma unroll
        for (int rr = 0; rr < 8; rr++) { w[rr] = __expf(sdots[rr] - nm); wsum += w[rr]; }
        Z = Z * scale + wsum;
        acc0 *= scale; acc1 *= scale; acc2 *= scale;
#pragma unroll
        for (int rr = 0; rr < 8; rr++) {
            acc0 += w[rr] * chunk[rr * VV + tid];
            acc1 += w[rr] * chunk[rr * VV + tid + 256];
            acc2 += w[rr] * chunk[rr * VV + tid + 512];
        }
        runmax = nm;
        __syncthreads();
    }
    size_t ob = (size_t)split * BB + b;
    g_axpart[ob * VV + tid] = acc0;
    g_axpart[ob * VV + tid + 256] = acc1;
    g_axpart[ob * VV + tid + 512] = acc2;
    if (tid == 0) { g_axm[ob] = runmax; g_axz[ob] = Z; }
}

// ---------------- K6: combine partials + full MLP head ----------------
__global__ __launch_bounds__(256) void finalK(const float* __restrict__ Wg, const float* __restrict__ bg,
                                              const float* __restrict__ Wfd, const float* __restrict__ bfd,
                                              const float* __restrict__ Wff, const float* __restrict__ bff,
                                              float* __restrict__ out) {
    int b = blockIdx.x, tid = threadIdx.x, wid = tid >> 5, lane = tid & 31;
    __shared__ float c1[2 * VV];   // [mean1 , atty]
    __shared__ float c2[2 * VV];   // [mean2 , attx]
    __shared__ float o_s[2 * HH];
    __shared__ float h_s[HH];
    float col512 = g_row[b * TT + 512];
    float wy512 = g_wy[b * TT + 512];
    float m[NSPLIT], z[NSPLIT];
#pragma unroll
    for (int i = 0; i < NSPLIT; i++) { m[i] = g_axm[i * BB + b]; z[i] = g_axz[i * BB + b]; }
    float M = col512;
#pragma unroll
    for (int i = 0; i < NSPLIT; i++) M = fmaxf(M, m[i]);
    float e5 = __expf(col512 - M);
    float Ztot = e5;
    float e[NSPLIT];
#pragma unroll
    for (int i = 0; i < NSPLIT; i++) { e[i] = __expf(m[i] - M); Ztot += e[i] * z[i]; }
    float inv = 1.f / Ztot;
    for (int v = tid; v < VV; v += 256) {
        float m1v = g_mean1[(size_t)b * VV + v];
        float m2v = g_mean2[(size_t)b * VV + v];
        float ax = e5 * m1v;
        float ay = wy512 * m2v;
#pragma unroll
        for (int i = 0; i < NSPLIT; i++) {
            ax += e[i] * g_axpart[((size_t)i * BB + b) * VV + v];
            ay += g_aypart[((size_t)i * BB + b) * VV + v];
        }
        c1[v] = m1v; c1[VV + v] = ay;
        c2[v] = m2v; c2[VV + v] = ax * inv;
    }
    __syncthreads();
    // o1/o2: 100 dot products of length 1536 against Wg rows
    for (int task = wid; task < 2 * HH; task += 8) {
        int which = task >= HH;
        int h = which ? task - HH : task;
        const float* c = which ? c2 : c1;
        float dot = 0.f;
        for (int j = lane; j < 2 * VV; j += 32) dot += Wg[h * 2 * VV + j] * c[j];
#pragma unroll
        for (int o = 16; o; o >>= 1) dot += __shfl_xor_sync(0xffffffffu, dot, o);
        if (lane == 0) o_s[which * HH + h] = bg[h] + dot;
    }
    __syncthreads();
    if (tid < HH) {
        float hv = bfd[tid];
#pragma unroll 4
        for (int k = 0; k < 2 * HH; k++) hv += Wfd[tid * 2 * HH + k] * o_s[k];
        h_s[tid] = fmaxf(hv, 0.f);
    }
    __syncthreads();
    if (tid == 0) {
        float l = bff[0];
#pragma unroll 5
        for (int j = 0; j < HH; j++) l += Wff[j] * h_s[j];
        out[b] = 1.f / (1.f + expf(-l));
    }
}

// ---------------- launch ----------------
extern "C" void kernel_launch(void* const* d_in, const int* in_sizes, int n_in,
                              void* d_out, int out_size) {
    const float* out1 = (const float*)d_in[0];
    const float* out2 = (const float*)d_in[1];
    const float* Wg  = (const float*)d_in[2];
    const float* bg  = (const float*)d_in[3];
    const float* Wfd = (const float*)d_in[4];
    const float* bfd = (const float*)d_in[5];
    const float* Wff = (const float*)d_in[6];
    const float* bff = (const float*)d_in[7];
    float* out = (float*)d_out;

    dim3 gp(NSPLIT, BB);
    dim3 gp2(NSPLIT, BB, 2);
    meanPartK<<<gp, 192>>>(out1);
    meanRowPartK<<<gp, 256>>>(out2);
    prepK<<<BB, 256>>>();
    softmaxBK<<<TT, 256>>>();
    attK<<<gp2, 256>>>(out1, out2);
    finalK<<<BB, 256>>>(Wg, bg, Wfd, bfd, Wff, bff, out);
}